// round 11
// baseline (speedup 1.0000x reference)
#include <cuda_runtime.h>
#include <cuda_fp16.h>
#include <mma.h>
#include <cstdint>

using namespace nvcuda;

#define N_NODES  100000
#define N_EDGES  3200000
#define IN_DIM   256
#define UNITS    128
#define CAP      128          // max edges per row bin (avg 32; Poisson-safe)
#define N_PAD    100096       // 782*128, padded so GEMM tiles can overread

// Device-global scratch (allocation-free)
__device__ __half g_xh[(size_t)N_PAD * IN_DIM];     // 51.3 MB: fp16 x
__device__ __half g_wh[IN_DIM * UNITS];             // fp16 W
__device__ __half g_h[(size_t)N_NODES * UNITS];     // 25.6 MB: h = x @ W
__device__ int    g_cnt[N_NODES];
__device__ int2   g_bins[(size_t)N_NODES * CAP];    // 102.4 MB row bins

// ---------------------------------------------------------------------------
// fp32 -> fp16 converters
// ---------------------------------------------------------------------------
__global__ __launch_bounds__(256)
void convert_x_kernel(const float* __restrict__ x) {
    // 25.6M floats = 6.4M float4; grid-stride
    const int n4 = N_NODES * IN_DIM / 4;
    for (int i = blockIdx.x * blockDim.x + threadIdx.x; i < n4;
         i += gridDim.x * blockDim.x) {
        float4 v = *(const float4*)(x + (size_t)i * 4);
        __half2 h0 = __floats2half2_rn(v.x, v.y);
        __half2 h1 = __floats2half2_rn(v.z, v.w);
        *(uint2*)(g_xh + (size_t)i * 4) =
            make_uint2(*(unsigned*)&h0, *(unsigned*)&h1);
    }
}

__global__ __launch_bounds__(256)
void convert_w_kernel(const float* __restrict__ W) {
    int i = blockIdx.x * blockDim.x + threadIdx.x;   // float4 index
    if (i < IN_DIM * UNITS / 4) {
        float4 v = *(const float4*)(W + (size_t)i * 4);
        __half2 h0 = __floats2half2_rn(v.x, v.y);
        __half2 h1 = __floats2half2_rn(v.z, v.w);
        *(uint2*)(g_wh + (size_t)i * 4) =
            make_uint2(*(unsigned*)&h0, *(unsigned*)&h1);
    }
}

// ---------------------------------------------------------------------------
// GEMM: h[N,128] = xh[N,256] @ wh[256,128] via wmma (HMMA), fp32 accum,
// fp16 store. CTA tile 128x128, BK=64, 256 threads, 2-stage cp.async.
// ---------------------------------------------------------------------------
#define BK        64
#define AS_STRIDE 72                      // halves; 144 B rows
#define BS_STRIDE 136                     // halves; 272 B rows
#define A_BYTES   (128 * AS_STRIDE * 2)   // 18432
#define B_BYTES   (BK * BS_STRIDE * 2)    // 17408
#define STAGE_BYTES (A_BYTES + B_BYTES)   // 35840
#define CS_STRIDE 132                     // floats; 528 B rows
#define SM_EPI_BYTES  (128 * CS_STRIDE * 4)       // 67584
#define SM_PIPE_BYTES (2 * STAGE_BYTES)           // 71680
#define SM_GEMM_TOTAL (SM_PIPE_BYTES > SM_EPI_BYTES ? SM_PIPE_BYTES : SM_EPI_BYTES)

__device__ __forceinline__ void cp16(uint32_t dst_smem, const void* src) {
    asm volatile("cp.async.cg.shared.global [%0], [%1], 16;"
                 :: "r"(dst_smem), "l"(src));
}

__global__ __launch_bounds__(256)
void gemm_kernel() {
    extern __shared__ char smem[];
    uint32_t sbase;
    asm("{ .reg .u64 t; cvta.to.shared.u64 t, %1; cvt.u32.u64 %0, t; }"
        : "=r"(sbase) : "l"(smem));

    const int tid  = threadIdx.x;
    const int wid  = tid >> 5;
    const int block_row = blockIdx.x * 128;
    const int warp_m = wid >> 1;      // 0..3
    const int warp_n = wid & 1;       // 0..1

    // Per-thread load coordinates (16B chunks)
    const int a_row = tid >> 3;           // with +32 step: 4 chunks
    const int a_c   = tid & 7;            // 0..7 (8 chunks of 16B per 128B row)
    const int b_row = tid >> 4;           // with +16 step: 4 chunks
    const int b_c   = tid & 15;           // 0..15 (16 chunks per 256B row)

    auto stage_load = [&](int s, int kk) {
        uint32_t st = sbase + s * STAGE_BYTES;
        #pragma unroll
        for (int it = 0; it < 4; it++) {
            int row = a_row + it * 32;
            cp16(st + row * (AS_STRIDE * 2) + a_c * 16,
                 g_xh + (size_t)(block_row + row) * IN_DIM + kk + a_c * 8);
        }
        #pragma unroll
        for (int it = 0; it < 4; it++) {
            int k = b_row + it * 16;
            cp16(st + A_BYTES + k * (BS_STRIDE * 2) + b_c * 16,
                 g_wh + (size_t)(kk + k) * UNITS + b_c * 8);
        }
        asm volatile("cp.async.commit_group;");
    };

    wmma::fragment<wmma::accumulator, 16, 16, 16, float> acc[2][4];
    #pragma unroll
    for (int i = 0; i < 2; i++)
        #pragma unroll
        for (int j = 0; j < 4; j++)
            wmma::fill_fragment(acc[i][j], 0.0f);

    stage_load(0, 0);

    #pragma unroll
    for (int kt = 0; kt < IN_DIM / BK; kt++) {
        if (kt + 1 < IN_DIM / BK) {
            stage_load((kt + 1) & 1, (kt + 1) * BK);
            asm volatile("cp.async.wait_group 1;");
        } else {
            asm volatile("cp.async.wait_group 0;");
        }
        __syncthreads();

        const __half* As = (const __half*)(smem + (kt & 1) * STAGE_BYTES);
        const __half* Bs = (const __half*)(smem + (kt & 1) * STAGE_BYTES + A_BYTES);

        #pragma unroll
        for (int k0 = 0; k0 < BK / 16; k0++) {
            wmma::fragment<wmma::matrix_a, 16, 16, 16, __half, wmma::row_major> af[2];
            #pragma unroll
            for (int i = 0; i < 2; i++)
                wmma::load_matrix_sync(af[i],
                    As + (warp_m * 32 + i * 16) * AS_STRIDE + k0 * 16, AS_STRIDE);
            #pragma unroll
            for (int j = 0; j < 4; j++) {
                wmma::fragment<wmma::matrix_b, 16, 16, 16, __half, wmma::row_major> bf;
                wmma::load_matrix_sync(bf,
                    Bs + (k0 * 16) * BS_STRIDE + warp_n * 64 + j * 16, BS_STRIDE);
                #pragma unroll
                for (int i = 0; i < 2; i++)
                    wmma::mma_sync(acc[i][j], af[i], bf, acc[i][j]);
            }
        }
        __syncthreads();
    }

    // Epilogue: stage f32 accum in SMEM (reuses pipeline buffers), convert.
    float* Cs = (float*)smem;
    #pragma unroll
    for (int i = 0; i < 2; i++)
        #pragma unroll
        for (int j = 0; j < 4; j++)
            wmma::store_matrix_sync(
                Cs + (warp_m * 32 + i * 16) * CS_STRIDE + warp_n * 64 + j * 16,
                acc[i][j], CS_STRIDE, wmma::mem_row_major);
    __syncthreads();

    #pragma unroll
    for (int it = 0; it < 16; it++) {
        int e   = tid + it * 256;
        int row = e >> 5;
        int c4  = e & 31;
        int grow = block_row + row;
        if (grow < N_NODES) {
            float4 v = *(float4*)(Cs + row * CS_STRIDE + c4 * 4);
            __half2 h0 = __floats2half2_rn(v.x, v.y);
            __half2 h1 = __floats2half2_rn(v.z, v.w);
            *(uint2*)(g_h + (size_t)grow * UNITS + c4 * 4) =
                make_uint2(*(unsigned*)&h0, *(unsigned*)&h1);
        }
    }
}

// ---------------------------------------------------------------------------
// Single-pass binning: p = atomicAdd(cnt[row]); bins[row*CAP+p] = {col,val}.
// ---------------------------------------------------------------------------
__global__ __launch_bounds__(256)
void fill_bins_kernel(const int* __restrict__ rows,
                      const int* __restrict__ cols,
                      const float* __restrict__ vals,
                      int n_edges) {
    int i4 = blockIdx.x * blockDim.x + threadIdx.x;
    int base = i4 * 4;
    if (base + 4 <= n_edges) {
        int4   r = *(const int4*)(rows + base);
        int4   c = *(const int4*)(cols + base);
        float4 v = *(const float4*)(vals + base);
        int p0 = atomicAdd(&g_cnt[r.x], 1);
        int p1 = atomicAdd(&g_cnt[r.y], 1);
        int p2 = atomicAdd(&g_cnt[r.z], 1);
        int p3 = atomicAdd(&g_cnt[r.w], 1);
        if (p0 < CAP) g_bins[(size_t)r.x * CAP + p0] = make_int2(c.x, __float_as_int(v.x));
        if (p1 < CAP) g_bins[(size_t)r.y * CAP + p1] = make_int2(c.y, __float_as_int(v.y));
        if (p2 < CAP) g_bins[(size_t)r.z * CAP + p2] = make_int2(c.z, __float_as_int(v.z));
        if (p3 < CAP) g_bins[(size_t)r.w * CAP + p3] = make_int2(c.w, __float_as_int(v.w));
    } else {
        for (int i = base; i < n_edges; i++) {
            int r = rows[i];
            int p = atomicAdd(&g_cnt[r], 1);
            if (p < CAP)
                g_bins[(size_t)r * CAP + p] = make_int2(cols[i], __float_as_int(vals[i]));
        }
    }
}

// ---------------------------------------------------------------------------
// Atomic-free reduce: one warp per row, lane owns 4 units (fp16 gather,
// fp32 accumulate), fused ReLU.
// ---------------------------------------------------------------------------
__device__ __forceinline__ void acc_edge(float4& a, uint2 hv, float v) {
    float2 f0 = __half22float2(*(__half2*)&hv.x);
    float2 f1 = __half22float2(*(__half2*)&hv.y);
    a.x = fmaf(v, f0.x, a.x);
    a.y = fmaf(v, f0.y, a.y);
    a.z = fmaf(v, f1.x, a.z);
    a.w = fmaf(v, f1.y, a.w);
}

__global__ __launch_bounds__(256)
void reduce_kernel(float* __restrict__ out) {
    int row  = (blockIdx.x * blockDim.x + threadIdx.x) >> 5;
    int lane = threadIdx.x & 31;
    if (row >= N_NODES) return;

    int cnt = g_cnt[row];
    if (cnt > CAP) cnt = CAP;
    const int2* bin = g_bins + (size_t)row * CAP;

    const uint2* hb = (const uint2*)g_h;
    float4 acc = make_float4(0.f, 0.f, 0.f, 0.f);

    int i = 0;
    for (; i + 4 <= cnt; i += 4) {
        int2 p0 = bin[i];
        int2 p1 = bin[i + 1];
        int2 p2 = bin[i + 2];
        int2 p3 = bin[i + 3];
        uint2 h0 = hb[(size_t)p0.x * 32 + lane];
        uint2 h1 = hb[(size_t)p1.x * 32 + lane];
        uint2 h2 = hb[(size_t)p2.x * 32 + lane];
        uint2 h3 = hb[(size_t)p3.x * 32 + lane];
        acc_edge(acc, h0, __int_as_float(p0.y));
        acc_edge(acc, h1, __int_as_float(p1.y));
        acc_edge(acc, h2, __int_as_float(p2.y));
        acc_edge(acc, h3, __int_as_float(p3.y));
    }
    for (; i < cnt; i++) {
        int2 p = bin[i];
        uint2 h = hb[(size_t)p.x * 32 + lane];
        acc_edge(acc, h, __int_as_float(p.y));
    }

    float4 o;
    o.x = fmaxf(acc.x, 0.f);
    o.y = fmaxf(acc.y, 0.f);
    o.z = fmaxf(acc.z, 0.f);
    o.w = fmaxf(acc.w, 0.f);
    ((float4*)out)[(size_t)row * 32 + lane] = o;
}

extern "C" void kernel_launch(void* const* d_in, const int* in_sizes, int n_in,
                              void* d_out, int out_size) {
    const float* x        = (const float*)d_in[0];
    const float* W        = (const float*)d_in[1];
    const int*   adj_rows = (const int*)d_in[2];
    const int*   adj_cols = (const int*)d_in[3];
    const float* adj_vals = (const float*)d_in[4];
    float* out = (float*)d_out;

    int n_edges = in_sizes[2];

    static bool inited = false;
    static void* cnt_ptr = nullptr;
    static cudaStream_t s2;
    static cudaEvent_t ev_fork, ev_join;
    if (!inited) {
        cudaFuncSetAttribute(gemm_kernel,
                             cudaFuncAttributeMaxDynamicSharedMemorySize,
                             SM_GEMM_TOTAL);
        cudaGetSymbolAddress(&cnt_ptr, g_cnt);
        cudaStreamCreateWithFlags(&s2, cudaStreamNonBlocking);
        cudaEventCreateWithFlags(&ev_fork, cudaEventDisableTiming);
        cudaEventCreateWithFlags(&ev_join, cudaEventDisableTiming);
        inited = true;
    }

    // Fork: convert + GEMM on side stream; binning on main stream.
    cudaEventRecord(ev_fork, 0);
    cudaStreamWaitEvent(s2, ev_fork, 0);
    convert_w_kernel<<<(IN_DIM * UNITS / 4 + 255) / 256, 256, 0, s2>>>(W);
    convert_x_kernel<<<1184, 256, 0, s2>>>(x);   // 8 blocks/SM
    gemm_kernel<<<(N_PAD) / 128, 256, SM_GEMM_TOTAL, s2>>>();
    cudaEventRecord(ev_join, s2);

    cudaMemsetAsync(cnt_ptr, 0, N_NODES * sizeof(int), 0);
    int e4 = (n_edges + 3) / 4;
    fill_bins_kernel<<<(e4 + 255) / 256, 256>>>(adj_rows, adj_cols,
                                                adj_vals, n_edges);

    // Join: reduce needs both g_h (s2) and g_bins/g_cnt (main).
    cudaStreamWaitEvent(0, ev_join, 0);
    reduce_kernel<<<(N_NODES + 7) / 8, 256>>>(out);
}

// round 14
// speedup vs baseline: 1.0723x; 1.0723x over previous
#include <cuda_runtime.h>
#include <cuda_fp16.h>
#include <mma.h>
#include <cstdint>

using namespace nvcuda;

#define N_NODES  100000
#define N_EDGES  3200000
#define IN_DIM   256
#define UNITS    128
#define CAP      128          // max edges per row bin (avg 32; Poisson-safe)
#define N_TILES  782          // ceil(100000/128)

// Device-global scratch (allocation-free)
__device__ __half g_h[(size_t)N_NODES * UNITS];     // 25.6 MB: h = x @ W
__device__ int    g_cnt[N_NODES];
__device__ int2   g_bins[(size_t)N_NODES * CAP];    // 102.4 MB row bins

// ---------------------------------------------------------------------------
// GEMM: h[N,128] = x[N,256] @ W[256,128] via wmma (HMMA), fp32 accum,
// fp16 store. Persistent: grid=148, CTA loops over 128-row tiles.
// W resident in SMEM; A register-double-buffered (load overlaps MMA).
// ---------------------------------------------------------------------------
#define BK        64
#define AS_STRIDE 72                           // halves; 144 B rows
#define BS_STRIDE 136                          // halves; 272 B rows
#define A_STAGE_BYTES (128 * AS_STRIDE * 2)    // 18432
#define SM_B_OFF   (2 * A_STAGE_BYTES)         // 36864
#define SM_B_BYTES (IN_DIM * BS_STRIDE * 2)    // 69632
#define SM_C_OFF   (SM_B_OFF + SM_B_BYTES)     // 106496
#define CS_STRIDE 132                          // floats; 528 B rows
#define SM_C_BYTES (128 * CS_STRIDE * 4)       // 67584
#define SM_GEMM_TOTAL (SM_C_OFF + SM_C_BYTES)  // 174080

__global__ __launch_bounds__(256)
void gemm_kernel(const float* __restrict__ x, const float* __restrict__ W) {
    extern __shared__ char smem[];
    __half* Bs = (__half*)(smem + SM_B_OFF);   // [256][BS_STRIDE] resident W
    float*  Cs = (float*)(smem + SM_C_OFF);    // [128][CS_STRIDE] epilogue

    const int tid  = threadIdx.x;
    const int wid  = tid >> 5;
    const int warp_m = wid >> 1;      // 0..3
    const int warp_n = wid & 1;       // 0..1

    // One-time: W fp32 -> Bs fp16. 256 rows x 32 float4 = 8192; 32/thread.
    #pragma unroll
    for (int it = 0; it < 32; it++) {
        int e  = tid + it * 256;
        int k  = e >> 5;
        int n4 = e & 31;
        float4 v = *(const float4*)(W + (size_t)k * UNITS + n4 * 4);
        __half2 h0 = __floats2half2_rn(v.x, v.y);
        __half2 h1 = __floats2half2_rn(v.z, v.w);
        *(uint2*)(Bs + k * BS_STRIDE + n4 * 4) =
            make_uint2(*(unsigned*)&h0, *(unsigned*)&h1);
    }
    __syncthreads();

    // A-load mapping: e = tid + it*256; row = e>>4, c4 = e&15 (16 f4/row)
    const int a_rows[8] = { (tid + 0*256) >> 4, (tid + 1*256) >> 4,
                            (tid + 2*256) >> 4, (tid + 3*256) >> 4,
                            (tid + 4*256) >> 4, (tid + 5*256) >> 4,
                            (tid + 6*256) >> 4, (tid + 7*256) >> 4 };
    const int a_c4 = tid & 15;   // same for all its since stride 256 keeps low 4 bits

    uint2 pa[8];
    auto load_a = [&](int block_row, int kk) {
        #pragma unroll
        for (int it = 0; it < 8; it++) {
            int grow = block_row + a_rows[it];
            float4 v = make_float4(0.f, 0.f, 0.f, 0.f);
            if (grow < N_NODES)
                v = *(const float4*)(x + (size_t)grow * IN_DIM + kk + a_c4 * 4);
            __half2 h0 = __floats2half2_rn(v.x, v.y);
            __half2 h1 = __floats2half2_rn(v.z, v.w);
            pa[it] = make_uint2(*(unsigned*)&h0, *(unsigned*)&h1);
        }
    };
    auto store_a = [&](int s) {
        __half* As = (__half*)(smem + s * A_STAGE_BYTES);
        #pragma unroll
        for (int it = 0; it < 8; it++)
            *(uint2*)(As + a_rows[it] * AS_STRIDE + a_c4 * 4) = pa[it];
    };

    for (int tile = blockIdx.x; tile < N_TILES; tile += gridDim.x) {
        const int block_row = tile * 128;

        wmma::fragment<wmma::accumulator, 16, 16, 16, float> acc[2][4];
        #pragma unroll
        for (int i = 0; i < 2; i++)
            #pragma unroll
            for (int j = 0; j < 4; j++)
                wmma::fill_fragment(acc[i][j], 0.0f);

        load_a(block_row, 0);

        #pragma unroll
        for (int kt = 0; kt < IN_DIM / BK; kt++) {
            store_a(kt & 1);
            __syncthreads();
            if (kt + 1 < IN_DIM / BK)
                load_a(block_row, (kt + 1) * BK);   // overlaps MMA below

            const __half* As = (const __half*)(smem + (kt & 1) * A_STAGE_BYTES);
            #pragma unroll
            for (int k0 = 0; k0 < BK / 16; k0++) {
                wmma::fragment<wmma::matrix_a, 16, 16, 16, __half,
                               wmma::row_major> af[2];
                #pragma unroll
                for (int i = 0; i < 2; i++)
                    wmma::load_matrix_sync(af[i],
                        As + (warp_m * 32 + i * 16) * AS_STRIDE + k0 * 16,
                        AS_STRIDE);
                #pragma unroll
                for (int j = 0; j < 4; j++) {
                    wmma::fragment<wmma::matrix_b, 16, 16, 16, __half,
                                   wmma::row_major> bf;
                    wmma::load_matrix_sync(bf,
                        Bs + (kt * BK + k0 * 16) * BS_STRIDE + warp_n * 64 + j * 16,
                        BS_STRIDE);
                    #pragma unroll
                    for (int i = 0; i < 2; i++)
                        wmma::mma_sync(acc[i][j], af[i], bf, acc[i][j]);
                }
            }
        }

        // Epilogue (Cs is a separate SMEM region; no pipe-buffer hazard)
        __syncthreads();
        #pragma unroll
        for (int i = 0; i < 2; i++)
            #pragma unroll
            for (int j = 0; j < 4; j++)
                wmma::store_matrix_sync(
                    Cs + (warp_m * 32 + i * 16) * CS_STRIDE + warp_n * 64 + j * 16,
                    acc[i][j], CS_STRIDE, wmma::mem_row_major);
        __syncthreads();

        #pragma unroll
        for (int it = 0; it < 16; it++) {
            int e   = tid + it * 256;
            int row = e >> 5;
            int c4  = e & 31;
            int grow = block_row + row;
            if (grow < N_NODES) {
                float4 v = *(float4*)(Cs + row * CS_STRIDE + c4 * 4);
                __half2 h0 = __floats2half2_rn(v.x, v.y);
                __half2 h1 = __floats2half2_rn(v.z, v.w);
                *(uint2*)(g_h + (size_t)grow * UNITS + c4 * 4) =
                    make_uint2(*(unsigned*)&h0, *(unsigned*)&h1);
            }
        }
        __syncthreads();
    }
}

// ---------------------------------------------------------------------------
// Single-pass binning: p = atomicAdd(cnt[row]); bins[row*CAP+p] = {col,val}.
// ---------------------------------------------------------------------------
__global__ __launch_bounds__(256)
void fill_bins_kernel(const int* __restrict__ rows,
                      const int* __restrict__ cols,
                      const float* __restrict__ vals,
                      int n_edges) {
    int i4 = blockIdx.x * blockDim.x + threadIdx.x;
    int base = i4 * 4;
    if (base + 4 <= n_edges) {
        int4   r = *(const int4*)(rows + base);
        int4   c = *(const int4*)(cols + base);
        float4 v = *(const float4*)(vals + base);
        int p0 = atomicAdd(&g_cnt[r.x], 1);
        int p1 = atomicAdd(&g_cnt[r.y], 1);
        int p2 = atomicAdd(&g_cnt[r.z], 1);
        int p3 = atomicAdd(&g_cnt[r.w], 1);
        if (p0 < CAP) g_bins[(size_t)r.x * CAP + p0] = make_int2(c.x, __float_as_int(v.x));
        if (p1 < CAP) g_bins[(size_t)r.y * CAP + p1] = make_int2(c.y, __float_as_int(v.y));
        if (p2 < CAP) g_bins[(size_t)r.z * CAP + p2] = make_int2(c.z, __float_as_int(v.z));
        if (p3 < CAP) g_bins[(size_t)r.w * CAP + p3] = make_int2(c.w, __float_as_int(v.w));
    } else {
        for (int i = base; i < n_edges; i++) {
            int r = rows[i];
            int p = atomicAdd(&g_cnt[r], 1);
            if (p < CAP)
                g_bins[(size_t)r * CAP + p] = make_int2(cols[i], __float_as_int(vals[i]));
        }
    }
}

// ---------------------------------------------------------------------------
// Atomic-free reduce: one warp per row, lane owns 4 units (fp16 gather,
// fp32 accumulate), fused ReLU.
// ---------------------------------------------------------------------------
__device__ __forceinline__ void acc_edge(float4& a, uint2 hv, float v) {
    float2 f0 = __half22float2(*(__half2*)&hv.x);
    float2 f1 = __half22float2(*(__half2*)&hv.y);
    a.x = fmaf(v, f0.x, a.x);
    a.y = fmaf(v, f0.y, a.y);
    a.z = fmaf(v, f1.x, a.z);
    a.w = fmaf(v, f1.y, a.w);
}

__global__ __launch_bounds__(256)
void reduce_kernel(float* __restrict__ out) {
    int row  = (blockIdx.x * blockDim.x + threadIdx.x) >> 5;
    int lane = threadIdx.x & 31;
    if (row >= N_NODES) return;

    int cnt = g_cnt[row];
    if (cnt > CAP) cnt = CAP;
    const int2* bin = g_bins + (size_t)row * CAP;

    const uint2* hb = (const uint2*)g_h;
    float4 acc = make_float4(0.f, 0.f, 0.f, 0.f);

    int i = 0;
    for (; i + 4 <= cnt; i += 4) {
        int2 p0 = bin[i];
        int2 p1 = bin[i + 1];
        int2 p2 = bin[i + 2];
        int2 p3 = bin[i + 3];
        uint2 h0 = hb[(size_t)p0.x * 32 + lane];
        uint2 h1 = hb[(size_t)p1.x * 32 + lane];
        uint2 h2 = hb[(size_t)p2.x * 32 + lane];
        uint2 h3 = hb[(size_t)p3.x * 32 + lane];
        acc_edge(acc, h0, __int_as_float(p0.y));
        acc_edge(acc, h1, __int_as_float(p1.y));
        acc_edge(acc, h2, __int_as_float(p2.y));
        acc_edge(acc, h3, __int_as_float(p3.y));
    }
    for (; i < cnt; i++) {
        int2 p = bin[i];
        uint2 h = hb[(size_t)p.x * 32 + lane];
        acc_edge(acc, h, __int_as_float(p.y));
    }

    float4 o;
    o.x = fmaxf(acc.x, 0.f);
    o.y = fmaxf(acc.y, 0.f);
    o.z = fmaxf(acc.z, 0.f);
    o.w = fmaxf(acc.w, 0.f);
    ((float4*)out)[(size_t)row * 32 + lane] = o;
}

extern "C" void kernel_launch(void* const* d_in, const int* in_sizes, int n_in,
                              void* d_out, int out_size) {
    const float* x        = (const float*)d_in[0];
    const float* W        = (const float*)d_in[1];
    const int*   adj_rows = (const int*)d_in[2];
    const int*   adj_cols = (const int*)d_in[3];
    const float* adj_vals = (const float*)d_in[4];
    float* out = (float*)d_out;

    int n_edges = in_sizes[2];

    static bool inited = false;
    static void* cnt_ptr = nullptr;
    static cudaStream_t s2;
    static cudaEvent_t ev_fork, ev_join;
    if (!inited) {
        cudaFuncSetAttribute(gemm_kernel,
                             cudaFuncAttributeMaxDynamicSharedMemorySize,
                             SM_GEMM_TOTAL);
        cudaGetSymbolAddress(&cnt_ptr, g_cnt);
        cudaStreamCreateWithFlags(&s2, cudaStreamNonBlocking);
        cudaEventCreateWithFlags(&ev_fork, cudaEventDisableTiming);
        cudaEventCreateWithFlags(&ev_join, cudaEventDisableTiming);
        inited = true;
    }

    // Fork: persistent GEMM (1 CTA/SM, regs left for fill co-residency).
    cudaEventRecord(ev_fork, 0);
    cudaStreamWaitEvent(s2, ev_fork, 0);
    gemm_kernel<<<148, 256, SM_GEMM_TOTAL, s2>>>(x, W);
    cudaEventRecord(ev_join, s2);

    cudaMemsetAsync(cnt_ptr, 0, N_NODES * sizeof(int), 0);
    int e4 = (n_edges + 3) / 4;
    fill_bins_kernel<<<(e4 + 255) / 256, 256>>>(adj_rows, adj_cols,
                                                adj_vals, n_edges);

    // Join: reduce needs both g_h (s2) and g_bins/g_cnt (main).
    cudaStreamWaitEvent(0, ev_join, 0);
    reduce_kernel<<<(N_NODES + 7) / 8, 256>>>(out);
}